// round 1
// baseline (speedup 1.0000x reference)
#include <cuda_runtime.h>
#include <math.h>

#define NTOK 16384
#define CDIM 8192
#define HDIM 2048
#define IDIM 8192

// Scratch (allocation-free rule: __device__ globals)
__device__ float g_h[(size_t)CDIM * IDIM];      // 256 MB: silu(gate)*up
__device__ float g_down[(size_t)CDIM * HDIM];   // 64 MB: down-proj in compact space

#define BM 128
#define BN 128
#define BK 16
#define TM 8
#define TN 8
#define PAD 4

// ---------------------------------------------------------------------------
// Kernel 1: fused gather + dual GEMM (gate, up) + SiLU*up epilogue -> g_h
//   gate[c,i] = sum_h x[fold_gather[c],h] * Wg[i,h]
//   up[c,i]   = sum_h x[fold_gather[c],h] * Wu[i,h]
//   g_h[c,i]  = silu(gate) * up
// ---------------------------------------------------------------------------
__global__ __launch_bounds__(256, 1)
void gemm12_kernel(const float* __restrict__ x,
                   const float* __restrict__ Wg,
                   const float* __restrict__ Wu,
                   const int* __restrict__ fold_gather)
{
    __shared__ float As [BK][BM + PAD];
    __shared__ float Bgs[BK][BN + PAD];
    __shared__ float Bus[BK][BN + PAD];
    __shared__ int   rows[BM];

    const int tid = threadIdx.x;
    const int m0  = blockIdx.y * BM;
    const int n0  = blockIdx.x * BN;
    const int tx  = tid & 15;
    const int ty  = tid >> 4;

    if (tid < BM) rows[tid] = fold_gather[m0 + tid];
    __syncthreads();

    float acc_g[TM][TN];
    float acc_u[TM][TN];
#pragma unroll
    for (int i = 0; i < TM; i++)
#pragma unroll
        for (int j = 0; j < TN; j++) { acc_g[i][j] = 0.f; acc_u[i][j] = 0.f; }

    for (int k0 = 0; k0 < HDIM; k0 += BK) {
        // 128 rows x 16 cols per tile = 512 float4; 2 float4 per thread per matrix
#pragma unroll
        for (int i = 0; i < 2; i++) {
            int idx = tid + i * 256;
            int r   = idx >> 2;
            int c4  = (idx & 3) * 4;

            float4 va = *reinterpret_cast<const float4*>(
                x + (size_t)rows[r] * HDIM + k0 + c4);
            As[c4 + 0][r] = va.x; As[c4 + 1][r] = va.y;
            As[c4 + 2][r] = va.z; As[c4 + 3][r] = va.w;

            float4 vg = *reinterpret_cast<const float4*>(
                Wg + (size_t)(n0 + r) * HDIM + k0 + c4);
            Bgs[c4 + 0][r] = vg.x; Bgs[c4 + 1][r] = vg.y;
            Bgs[c4 + 2][r] = vg.z; Bgs[c4 + 3][r] = vg.w;

            float4 vu = *reinterpret_cast<const float4*>(
                Wu + (size_t)(n0 + r) * HDIM + k0 + c4);
            Bus[c4 + 0][r] = vu.x; Bus[c4 + 1][r] = vu.y;
            Bus[c4 + 2][r] = vu.z; Bus[c4 + 3][r] = vu.w;
        }
        __syncthreads();

#pragma unroll
        for (int kk = 0; kk < BK; kk++) {
            float a[TM], bg[TN], bu[TN];
#pragma unroll
            for (int i = 0; i < TM; i++) a[i] = As[kk][ty * TM + i];
#pragma unroll
            for (int j = 0; j < TN; j++) {
                bg[j] = Bgs[kk][tx * TN + j];
                bu[j] = Bus[kk][tx * TN + j];
            }
#pragma unroll
            for (int i = 0; i < TM; i++)
#pragma unroll
                for (int j = 0; j < TN; j++) {
                    acc_g[i][j] = fmaf(a[i], bg[j], acc_g[i][j]);
                    acc_u[i][j] = fmaf(a[i], bu[j], acc_u[i][j]);
                }
        }
        __syncthreads();
    }

    // Epilogue: silu(gate) * up -> g_h, vectorized stores
#pragma unroll
    for (int i = 0; i < TM; i++) {
        size_t row = (size_t)(m0 + ty * TM + i) * IDIM + (n0 + tx * TN);
        float v[TN];
#pragma unroll
        for (int j = 0; j < TN; j++) {
            float g = acc_g[i][j];
            float s = g / (1.f + expf(-g));   // silu(g) = g * sigmoid(g)
            v[j] = s * acc_u[i][j];
        }
        *reinterpret_cast<float4*>(g_h + row)     = make_float4(v[0], v[1], v[2], v[3]);
        *reinterpret_cast<float4*>(g_h + row + 4) = make_float4(v[4], v[5], v[6], v[7]);
    }
}

// ---------------------------------------------------------------------------
// Kernel 2: down projection
//   g_down[c,h] = sum_i g_h[c,i] * Wd[h,i]
// ---------------------------------------------------------------------------
__global__ __launch_bounds__(256, 1)
void gemm3_kernel(const float* __restrict__ Wd)
{
    __shared__ float As[BK][BM + PAD];
    __shared__ float Bs[BK][BN + PAD];

    const int tid = threadIdx.x;
    const int m0  = blockIdx.y * BM;
    const int n0  = blockIdx.x * BN;
    const int tx  = tid & 15;
    const int ty  = tid >> 4;

    float acc[TM][TN];
#pragma unroll
    for (int i = 0; i < TM; i++)
#pragma unroll
        for (int j = 0; j < TN; j++) acc[i][j] = 0.f;

    for (int k0 = 0; k0 < IDIM; k0 += BK) {
#pragma unroll
        for (int i = 0; i < 2; i++) {
            int idx = tid + i * 256;
            int r   = idx >> 2;
            int c4  = (idx & 3) * 4;

            float4 va = *reinterpret_cast<const float4*>(
                g_h + (size_t)(m0 + r) * IDIM + k0 + c4);
            As[c4 + 0][r] = va.x; As[c4 + 1][r] = va.y;
            As[c4 + 2][r] = va.z; As[c4 + 3][r] = va.w;

            float4 vb = *reinterpret_cast<const float4*>(
                Wd + (size_t)(n0 + r) * IDIM + k0 + c4);
            Bs[c4 + 0][r] = vb.x; Bs[c4 + 1][r] = vb.y;
            Bs[c4 + 2][r] = vb.z; Bs[c4 + 3][r] = vb.w;
        }
        __syncthreads();

#pragma unroll
        for (int kk = 0; kk < BK; kk++) {
            float a[TM], b[TN];
#pragma unroll
            for (int i = 0; i < TM; i++) a[i] = As[kk][ty * TM + i];
#pragma unroll
            for (int j = 0; j < TN; j++) b[j] = Bs[kk][tx * TN + j];
#pragma unroll
            for (int i = 0; i < TM; i++)
#pragma unroll
                for (int j = 0; j < TN; j++)
                    acc[i][j] = fmaf(a[i], b[j], acc[i][j]);
        }
        __syncthreads();
    }

#pragma unroll
    for (int i = 0; i < TM; i++) {
        size_t row = (size_t)(m0 + ty * TM + i) * HDIM + (n0 + tx * TN);
        *reinterpret_cast<float4*>(g_down + row) =
            make_float4(acc[i][0], acc[i][1], acc[i][2], acc[i][3]);
        *reinterpret_cast<float4*>(g_down + row + 4) =
            make_float4(acc[i][4], acc[i][5], acc[i][6], acc[i][7]);
    }
}

// ---------------------------------------------------------------------------
// Kernel 3: scatter compact rows to all original token slots
//   out[t,:] = g_down[scatter_indices[t],:]
// ---------------------------------------------------------------------------
__global__ __launch_bounds__(256)
void scatter_kernel(const int* __restrict__ scatter_indices,
                    float* __restrict__ out)
{
    const int t = blockIdx.x;
    const int c = scatter_indices[t];
    const float4* src = reinterpret_cast<const float4*>(g_down + (size_t)c * HDIM);
    float4*       dst = reinterpret_cast<float4*>(out + (size_t)t * HDIM);
#pragma unroll
    for (int j = threadIdx.x; j < HDIM / 4; j += 256)
        dst[j] = src[j];
}

// ---------------------------------------------------------------------------
extern "C" void kernel_launch(void* const* d_in, const int* in_sizes, int n_in,
                              void* d_out, int out_size)
{
    const float* x  = (const float*)d_in[0];
    const float* Wg = (const float*)d_in[1];
    const float* Wu = (const float*)d_in[2];
    const float* Wd = (const float*)d_in[3];
    const int*   fg = (const int*)d_in[4];
    const int*   sc = (const int*)d_in[5];
    float*       out = (float*)d_out;

    dim3 grid12(IDIM / BN, CDIM / BM);   // 64 x 64
    gemm12_kernel<<<grid12, 256>>>(x, Wg, Wu, fg);

    dim3 grid3(HDIM / BN, CDIM / BM);    // 16 x 64
    gemm3_kernel<<<grid3, 256>>>(Wd);

    scatter_kernel<<<NTOK, 256>>>(sc, out);
}

// round 3
// speedup vs baseline: 2.9665x; 2.9665x over previous
#include <cuda_runtime.h>
#include <cuda_bf16.h>
#include <math.h>
#include <stdint.h>

#define NTOK 16384
#define CDIM 8192
#define HDIM 2048
#define IDIM 8192

// Scratch (allocation-free rule: __device__ globals)
__device__ float g_h[(size_t)CDIM * IDIM];      // 256 MB: silu(gate)*up
__device__ float g_down[(size_t)CDIM * HDIM];   // 64 MB

// ---------------------------------------------------------------------------
// helpers (plain sm_80-era PTX only — no 'a'-gated features)
// ---------------------------------------------------------------------------
__device__ __forceinline__ uint32_t smem_u32(const void* p) {
    return (uint32_t)__cvta_generic_to_shared(p);
}
__device__ __forceinline__ void ldsm4(uint32_t a, uint32_t& r0, uint32_t& r1,
                                      uint32_t& r2, uint32_t& r3) {
    asm volatile("ldmatrix.sync.aligned.m8n8.x4.shared.b16 {%0,%1,%2,%3}, [%4];"
                 : "=r"(r0), "=r"(r1), "=r"(r2), "=r"(r3) : "r"(a));
}
__device__ __forceinline__ void hmma(float* c, const uint32_t* a,
                                     uint32_t b0, uint32_t b1) {
    asm volatile(
        "mma.sync.aligned.m16n8k16.row.col.f32.bf16.bf16.f32 "
        "{%0,%1,%2,%3},{%4,%5,%6,%7},{%8,%9},{%0,%1,%2,%3};"
        : "+f"(c[0]), "+f"(c[1]), "+f"(c[2]), "+f"(c[3])
        : "r"(a[0]), "r"(a[1]), "r"(a[2]), "r"(a[3]), "r"(b0), "r"(b1));
}
// fp32 -> (hi, lo) bf16 split of 4 consecutive K elements; 8B packed stores
__device__ __forceinline__ void split_store(char* hi, char* lo, float4 v) {
    __nv_bfloat162 h0 = __floats2bfloat162_rn(v.x, v.y);
    __nv_bfloat162 h1 = __floats2bfloat162_rn(v.z, v.w);
    float2 f0 = __bfloat1622float2(h0);
    float2 f1 = __bfloat1622float2(h1);
    __nv_bfloat162 l0 = __floats2bfloat162_rn(v.x - f0.x, v.y - f0.y);
    __nv_bfloat162 l1 = __floats2bfloat162_rn(v.z - f1.x, v.w - f1.y);
    uint32_t h0u = *reinterpret_cast<uint32_t*>(&h0);
    uint32_t h1u = *reinterpret_cast<uint32_t*>(&h1);
    uint32_t l0u = *reinterpret_cast<uint32_t*>(&l0);
    uint32_t l1u = *reinterpret_cast<uint32_t*>(&l1);
    *reinterpret_cast<uint2*>(hi) = make_uint2(h0u, h1u);
    *reinterpret_cast<uint2*>(lo) = make_uint2(l0u, l1u);
}

// smem tile geometry: rows of 32 bf16 padded to 40 (80 bytes = 5x16B):
// conflict-free for ldmatrix (rows hit disjoint bank groups) and 16B-aligned.
#define ROWB 80
// k1 stage sections (row index * ROWB):  A_hi 0..127 | A_lo | Bg_hi | Bg_lo | Bu_hi | Bu_lo
#define K1_ALO   10240
#define K1_BGHI  20480
#define K1_BGLO  30720
#define K1_BUHI  40960
#define K1_BULO  51200
#define STAGE1   61440
#define SMEM1    (2 * STAGE1)
// k2 stage sections: A_hi | A_lo | B_hi | B_lo
#define K2_ALO   10240
#define K2_BHI   20480
#define K2_BLO   30720
#define STAGE2   40960
#define SMEM2    (2 * STAGE2)

#define NC1 (HDIM / 32)   // 64 chunks
#define NC2 (IDIM / 32)   // 256 chunks

__device__ __forceinline__ float silu(float g) { return g / (1.f + expf(-g)); }

// ---------------------------------------------------------------------------
// Kernel 1: gather + dual GEMM (gate,up) bf16-split-3 HMMA + SiLU epilogue
// CTA: 128 tokens x (128 gate cols + 128 up cols). 8 warps:
//   warps 0-3: gate, rows 32w..32w+31, all 128 cols
//   warps 4-7: up,   rows 32(w-4)..,   all 128 cols
// ---------------------------------------------------------------------------
__global__ __launch_bounds__(256)
void k1_gateup(const float* __restrict__ x,
               const float* __restrict__ Wg,
               const float* __restrict__ Wu,
               const int* __restrict__ fg)
{
    extern __shared__ __align__(128) char sm[];
    const uint32_t smb = smem_u32(sm);
    const int tid  = threadIdx.x;
    const int wid  = tid >> 5;
    const int lane = tid & 31;
    const int m0 = blockIdx.x * 128;   // m fastest -> B tiles L2-resident
    const int n0 = blockIdx.y * 128;

    // per-thread load geometry: 12 float4 per chunk (A:4, Bg:4, Bu:4)
    const int rbase = tid >> 3;            // 0..31
    const int c4    = (tid & 7) * 4;       // 0..28
    const float *pA[4], *pG[4], *pU[4];
    int sts[4];
#pragma unroll
    for (int j = 0; j < 4; j++) {
        int row = rbase + 32 * j;          // 0..127
        pA[j] = x  + (size_t)__ldg(fg + m0 + row) * HDIM + c4;
        pG[j] = Wg + (size_t)(n0 + row) * HDIM + c4;
        pU[j] = Wu + (size_t)(n0 + row) * HDIM + c4;
        sts[j] = row * ROWB + (tid & 7) * 8;
    }

    // ldmatrix lane geometry
    const int laneRow = ((lane >> 3) & 1) * 8 + (lane & 7);
    const int laneK   = (lane >> 4) * 16;
    const int R       = 32 * (wid & 3);
    const int bSec    = (wid >= 4) ? K1_BUHI : K1_BGHI;

    float acc[2][16][4];
#pragma unroll
    for (int f = 0; f < 2; f++)
#pragma unroll
        for (int n = 0; n < 16; n++)
#pragma unroll
            for (int q = 0; q < 4; q++) acc[f][n][q] = 0.f;

    // prologue: chunk 0 -> stage 0
    float4 rA[4], rG[4], rU[4];
#pragma unroll
    for (int j = 0; j < 4; j++) {
        rA[j] = *reinterpret_cast<const float4*>(pA[j]);
        rG[j] = *reinterpret_cast<const float4*>(pG[j]);
        rU[j] = *reinterpret_cast<const float4*>(pU[j]);
    }
    {
        char* st = sm;
#pragma unroll
        for (int j = 0; j < 4; j++) {
            split_store(st + sts[j],           st + K1_ALO  + sts[j], rA[j]);
            split_store(st + K1_BGHI + sts[j], st + K1_BGLO + sts[j], rG[j]);
            split_store(st + K1_BUHI + sts[j], st + K1_BULO + sts[j], rU[j]);
        }
    }

#pragma unroll 1
    for (int c = 0; c < NC1; c++) {
        __syncthreads();
        // stage next chunk's gmem into regs (latency hidden under MMA)
        if (c + 1 < NC1) {
            const int k0 = (c + 1) * 32;
#pragma unroll
            for (int j = 0; j < 4; j++) {
                rA[j] = *reinterpret_cast<const float4*>(pA[j] + k0);
                rG[j] = *reinterpret_cast<const float4*>(pG[j] + k0);
                rU[j] = *reinterpret_cast<const float4*>(pU[j] + k0);
            }
        }
        // MMA over current buffer
        const uint32_t sb = smb + (c & 1) * STAGE1;
#pragma unroll
        for (int s = 0; s < 2; s++) {
            const uint32_t ab = sb + (uint32_t)((R + laneRow) * ROWB + laneK + 32 * s);
            uint32_t ah[2][4], al[2][4];
            ldsm4(ab,                 ah[0][0], ah[0][1], ah[0][2], ah[0][3]);
            ldsm4(ab + 16 * ROWB,     ah[1][0], ah[1][1], ah[1][2], ah[1][3]);
            ldsm4(ab + K1_ALO,        al[0][0], al[0][1], al[0][2], al[0][3]);
            ldsm4(ab + K1_ALO + 16 * ROWB, al[1][0], al[1][1], al[1][2], al[1][3]);
#pragma unroll
            for (int gp = 0; gp < 8; gp++) {
                const uint32_t bb = sb + (uint32_t)(bSec +
                    (16 * gp + laneRow) * ROWB + laneK + 32 * s);
                uint32_t bh[4], bl[4];
                ldsm4(bb,         bh[0], bh[1], bh[2], bh[3]);
                ldsm4(bb + 10240, bl[0], bl[1], bl[2], bl[3]);
#pragma unroll
                for (int f = 0; f < 2; f++)
#pragma unroll
                    for (int h = 0; h < 2; h++) {
                        float* cc = acc[f][2 * gp + h];
                        hmma(cc, ah[f], bh[h], bh[2 + h]);
                        hmma(cc, ah[f], bl[h], bl[2 + h]);
                        hmma(cc, al[f], bh[h], bh[2 + h]);
                    }
            }
        }
        // store staged chunk into the other buffer
        if (c + 1 < NC1) {
            char* st = sm + ((c + 1) & 1) * STAGE1;
#pragma unroll
            for (int j = 0; j < 4; j++) {
                split_store(st + sts[j],           st + K1_ALO  + sts[j], rA[j]);
                split_store(st + K1_BGHI + sts[j], st + K1_BGLO + sts[j], rG[j]);
                split_store(st + K1_BUHI + sts[j], st + K1_BULO + sts[j], rU[j]);
            }
        }
    }

    // ---- epilogue: up warps park in smem; gate warps compute silu(g)*u ----
    __syncthreads();
    float* upbuf = reinterpret_cast<float*>(sm);   // 4 warps x 32 x 132 floats
    if (wid >= 4) {
        const int w = wid - 4;
#pragma unroll
        for (int f = 0; f < 2; f++)
#pragma unroll
            for (int n = 0; n < 16; n++) {
                int row = 16 * f + (lane >> 2);
                int col = 8 * n + (lane & 3) * 2;
                float* b0 = upbuf + w * 4224 + row * 132 + col;
                b0[0] = acc[f][n][0]; b0[1] = acc[f][n][1];
                float* b1 = b0 + 8 * 132;
                b1[0] = acc[f][n][2]; b1[1] = acc[f][n][3];
            }
    }
    __syncthreads();
    if (wid < 4) {
        const int w = wid;
#pragma unroll
        for (int f = 0; f < 2; f++)
#pragma unroll
            for (int n = 0; n < 16; n++) {
                int row = 16 * f + (lane >> 2);
                int col = 8 * n + (lane & 3) * 2;
                const float* b0 = upbuf + w * 4224 + row * 132 + col;
                const float* b1 = b0 + 8 * 132;
                float* o0 = g_h + (size_t)(m0 + 32 * w + row) * IDIM + n0 + col;
                float* o1 = o0 + (size_t)8 * IDIM;
                float2 v0 = make_float2(silu(acc[f][n][0]) * b0[0],
                                        silu(acc[f][n][1]) * b0[1]);
                float2 v1 = make_float2(silu(acc[f][n][2]) * b1[0],
                                        silu(acc[f][n][3]) * b1[1]);
                *reinterpret_cast<float2*>(o0) = v0;
                *reinterpret_cast<float2*>(o1) = v1;
            }
    }
}

// ---------------------------------------------------------------------------
// Kernel 2: down projection, bf16-split-3 HMMA.
// CTA: 128 x 128. 8 warps in 4m x 2n grid; warp tile 32 x 64 (acc 64/thread).
// ---------------------------------------------------------------------------
__global__ __launch_bounds__(256)
void k2_down(const float* __restrict__ Wd)
{
    extern __shared__ __align__(128) char sm[];
    const uint32_t smb = smem_u32(sm);
    const int tid  = threadIdx.x;
    const int wid  = tid >> 5;
    const int lane = tid & 31;
    const int m0 = blockIdx.x * 128;
    const int n0 = blockIdx.y * 128;

    const int rbase = tid >> 3;
    const int c4    = (tid & 7) * 4;
    const float *pA[4], *pB[4];
    int sts[4];
#pragma unroll
    for (int j = 0; j < 4; j++) {
        int row = rbase + 32 * j;
        pA[j] = g_h + (size_t)(m0 + row) * IDIM + c4;
        pB[j] = Wd  + (size_t)(n0 + row) * IDIM + c4;
        sts[j] = row * ROWB + (tid & 7) * 8;
    }

    const int laneRow = ((lane >> 3) & 1) * 8 + (lane & 7);
    const int laneK   = (lane >> 4) * 16;
    const int R       = 32 * (wid & 3);
    const int cb      = 64 * (wid >> 2);

    float acc[2][8][4];
#pragma unroll
    for (int f = 0; f < 2; f++)
#pragma unroll
        for (int n = 0; n < 8; n++)
#pragma unroll
            for (int q = 0; q < 4; q++) acc[f][n][q] = 0.f;

    float4 rA[4], rB[4];
#pragma unroll
    for (int j = 0; j < 4; j++) {
        rA[j] = *reinterpret_cast<const float4*>(pA[j]);
        rB[j] = *reinterpret_cast<const float4*>(pB[j]);
    }
    {
        char* st = sm;
#pragma unroll
        for (int j = 0; j < 4; j++) {
            split_store(st + sts[j],          st + K2_ALO + sts[j], rA[j]);
            split_store(st + K2_BHI + sts[j], st + K2_BLO + sts[j], rB[j]);
        }
    }

#pragma unroll 1
    for (int c = 0; c < NC2; c++) {
        __syncthreads();
        if (c + 1 < NC2) {
            const int k0 = (c + 1) * 32;
#pragma unroll
            for (int j = 0; j < 4; j++) {
                rA[j] = *reinterpret_cast<const float4*>(pA[j] + k0);
                rB[j] = *reinterpret_cast<const float4*>(pB[j] + k0);
            }
        }
        const uint32_t sb = smb + (c & 1) * STAGE2;
#pragma unroll
        for (int s = 0; s < 2; s++) {
            const uint32_t ab = sb + (uint32_t)((R + laneRow) * ROWB + laneK + 32 * s);
            uint32_t ah[2][4], al[2][4];
            ldsm4(ab,                      ah[0][0], ah[0][1], ah[0][2], ah[0][3]);
            ldsm4(ab + 16 * ROWB,          ah[1][0], ah[1][1], ah[1][2], ah[1][3]);
            ldsm4(ab + K2_ALO,             al[0][0], al[0][1], al[0][2], al[0][3]);
            ldsm4(ab + K2_ALO + 16 * ROWB, al[1][0], al[1][1], al[1][2], al[1][3]);
#pragma unroll
            for (int gp = 0; gp < 4; gp++) {
                const uint32_t bb = sb + (uint32_t)(K2_BHI +
                    (cb + 16 * gp + laneRow) * ROWB + laneK + 32 * s);
                uint32_t bh[4], bl[4];
                ldsm4(bb,         bh[0], bh[1], bh[2], bh[3]);
                ldsm4(bb + 10240, bl[0], bl[1], bl[2], bl[3]);
#pragma unroll
                for (int f = 0; f < 2; f++)
#pragma unroll
                    for (int h = 0; h < 2; h++) {
                        float* cc = acc[f][2 * gp + h];
                        hmma(cc, ah[f], bh[h], bh[2 + h]);
                        hmma(cc, ah[f], bl[h], bl[2 + h]);
                        hmma(cc, al[f], bh[h], bh[2 + h]);
                    }
            }
        }
        if (c + 1 < NC2) {
            char* st = sm + ((c + 1) & 1) * STAGE2;
#pragma unroll
            for (int j = 0; j < 4; j++) {
                split_store(st + sts[j],          st + K2_ALO + sts[j], rA[j]);
                split_store(st + K2_BHI + sts[j], st + K2_BLO + sts[j], rB[j]);
            }
        }
    }

    // epilogue: direct fp32 stores
#pragma unroll
    for (int f = 0; f < 2; f++)
#pragma unroll
        for (int n = 0; n < 8; n++) {
            int row = R + 16 * f + (lane >> 2);
            int col = n0 + cb + 8 * n + (lane & 3) * 2;
            float* o0 = g_down + (size_t)(m0 + row) * HDIM + col;
            float* o1 = o0 + (size_t)8 * HDIM;
            *reinterpret_cast<float2*>(o0) = make_float2(acc[f][n][0], acc[f][n][1]);
            *reinterpret_cast<float2*>(o1) = make_float2(acc[f][n][2], acc[f][n][3]);
        }
}

// ---------------------------------------------------------------------------
// Kernel 3: scatter compact rows to all original token slots
// ---------------------------------------------------------------------------
__global__ __launch_bounds__(256)
void scatter_kernel(const int* __restrict__ scatter_indices,
                    float* __restrict__ out)
{
    const int t = blockIdx.x;
    const int c = scatter_indices[t];
    const float4* src = reinterpret_cast<const float4*>(g_down + (size_t)c * HDIM);
    float4*       dst = reinterpret_cast<float4*>(out + (size_t)t * HDIM);
#pragma unroll
    for (int j = threadIdx.x; j < HDIM / 4; j += 256)
        dst[j] = src[j];
}

// ---------------------------------------------------------------------------
extern "C" void kernel_launch(void* const* d_in, const int* in_sizes, int n_in,
                              void* d_out, int out_size)
{
    const float* x  = (const float*)d_in[0];
    const float* Wg = (const float*)d_in[1];
    const float* Wu = (const float*)d_in[2];
    const float* Wd = (const float*)d_in[3];
    const int*   fg = (const int*)d_in[4];
    const int*   sc = (const int*)d_in[5];
    float*       out = (float*)d_out;

    cudaFuncSetAttribute(k1_gateup, cudaFuncAttributeMaxDynamicSharedMemorySize, SMEM1);
    cudaFuncSetAttribute(k2_down,   cudaFuncAttributeMaxDynamicSharedMemorySize, SMEM2);

    dim3 g1(CDIM / 128, IDIM / 128);   // (64 m, 64 n) — m fastest
    k1_gateup<<<g1, 256, SMEM1>>>(x, Wg, Wu, fg);

    dim3 g2(CDIM / 128, HDIM / 128);   // (64 m, 16 n)
    k2_down<<<g2, 256, SMEM2>>>(Wd);

    scatter_kernel<<<NTOK, 256>>>(sc, out);
}